// round 3
// baseline (speedup 1.0000x reference)
#include <cuda_runtime.h>
#include <math.h>

#define EPS 1e-5f

// ---------------- device scratch (no runtime allocation allowed) ----------------
__device__ float g_wm1[3456],    g_wv1[3456];
__device__ float g_wm2[147456],  g_wv2[147456];
__device__ float g_wm3[294912],  g_wv3[294912];
__device__ float g_wm4[589824],  g_wv4[589824];
__device__ float g_wm5[1179648], g_wv5[1179648];
__device__ float g_wm6[2359296], g_wv6[2359296];

__device__ float g_h1[33554432];  // [256,128,32,32]
__device__ float g_h2[8388608];   // [256,128,16,16]
__device__ float g_h3[16777216];  // [256,256,16,16]
__device__ float g_h4[4194304];   // [256,256,8,8]
__device__ float g_h5[8388608];   // [256,512,8,8]
__device__ float g_z6[2097152];   // [256,512,4,4]
__device__ float g_zbn[2097152];  // [256,8192]
__device__ float g_fc1o[262144];  // [256,1024]
__device__ float g_bnscale[512], g_bnshift[512];

// ---------------- packed f32x2 helpers ----------------
__device__ __forceinline__ unsigned long long bcast2(float x) {
    unsigned long long r;
    unsigned u = __float_as_uint(x);
    asm("mov.b64 %0, {%1, %1};" : "=l"(r) : "r"(u));
    return r;
}
__device__ __forceinline__ unsigned long long mul2(unsigned long long a, unsigned long long b) {
    unsigned long long d;
    asm("mul.rn.f32x2 %0, %1, %2;" : "=l"(d) : "l"(a), "l"(b));
    return d;
}
__device__ __forceinline__ void fma2(unsigned long long& d, unsigned long long a, unsigned long long b) {
    asm("fma.rn.f32x2 %0, %1, %2, %0;" : "+l"(d) : "l"(a), "l"(b));
}
__device__ __forceinline__ void unpack2(unsigned long long v, float& lo, float& hi) {
    unsigned ulo, uhi;
    asm("mov.b64 {%0, %1}, %2;" : "=r"(ulo), "=r"(uhi) : "l"(v));
    lo = __uint_as_float(ulo); hi = __uint_as_float(uhi);
}

// ---------------- weight distribution preprocessing (one launch) ----------------
__global__ void prep_all(const float* __restrict__ a1, const float* __restrict__ b1,
                         const float* __restrict__ a2, const float* __restrict__ b2,
                         const float* __restrict__ a3, const float* __restrict__ b3,
                         const float* __restrict__ a4, const float* __restrict__ b4,
                         const float* __restrict__ a5, const float* __restrict__ b5,
                         const float* __restrict__ a6, const float* __restrict__ b6)
{
    int i = blockIdx.x * blockDim.x + threadIdx.x;
    if (i >= 4574592) return;
    const float *A, *Bp; float *WM, *WV; int j;
    if (i < 150912) {
        if (i < 3456) { A = a1; Bp = b1; WM = g_wm1; WV = g_wv1; j = i; }
        else          { A = a2; Bp = b2; WM = g_wm2; WV = g_wv2; j = i - 3456; }
    } else if (i < 1035648) {
        if (i < 445824) { A = a3; Bp = b3; WM = g_wm3; WV = g_wv3; j = i - 150912; }
        else            { A = a4; Bp = b4; WM = g_wm4; WV = g_wv4; j = i - 445824; }
    } else {
        if (i < 2215296) { A = a5; Bp = b5; WM = g_wm5; WV = g_wv5; j = i - 1035648; }
        else             { A = a6; Bp = b6; WM = g_wm6; WV = g_wv6; j = i - 2215296; }
    }
    float p0 = 1.f / (1.f + expf(-A[j]));
    float sb = 1.f / (1.f + expf(-Bp[j]));
    float p1 = (1.f - p0) * sb;
    float m  = 2.f * p1 + p0 - 1.f;
    WM[j] = m;
    WV[j] = (1.f - p0) - m * m;
}

// ---------------- fused LR-conv layer, v2 microtile ----------------
// Each thread: CO_T output channels x PX_T consecutive output pixels (one row seg).
// m = conv(x, w_mean)+bias ; v = conv(x*x, w_var)
// LAST=false: out = erf(m / sqrt(2*(v+EPS)))   LAST=true: out = m + sqrt(v+EPS)*noise
template<int CIN, int COUT, int HIN, int WIN, int S, int TPH, int TPW, int NB,
         int CK, int CO_T, int PX_T, bool LAST, int THREADS>
__global__ void __launch_bounds__(THREADS)
conv_lr2(const float* __restrict__ in, const float* __restrict__ wm,
         const float* __restrict__ wv, const float* __restrict__ bias,
         float* __restrict__ out, const float* __restrict__ noise)
{
    constexpr int TCO  = 32;
    constexpr int HO   = HIN / S;
    constexpr int WO   = WIN / S;
    constexpr int IPH  = (TPH - 1) * S + 3;
    constexpr int IPW  = (((TPW - 1) * S + 3) + 3) & ~3;   // padded to 16B
    constexpr int SEG  = TPW / PX_T;
    constexpr int XS_N = NB * CK * IPH * IPW;
    constexpr int WS_N = CK * 9 * TCO;
    constexpr int NXV  = (PX_T - 1) * S + 3;               // x values per row needed
    constexpr int NF4  = (NXV + 3) / 4;
    constexpr int CP   = CO_T / 2;                         // channel pairs
    static_assert(THREADS == (TCO / CO_T) * (NB * TPH * SEG), "thread count mismatch");
    static_assert(NF4 * 4 <= IPW, "x vector load overruns row");
    static_assert((PX_T * S) % 4 == 0, "segment start misaligned");

    __shared__ __align__(16) float xs[XS_N];
    __shared__ __align__(16) float wsm[WS_N];
    __shared__ __align__(16) float wsv[WS_N];

    const int tid = threadIdx.x;
    constexpr int TILESX = WO / TPW;
    const int tileX  = blockIdx.x % TILESX;
    const int tileY  = blockIdx.x / TILESX;
    const int coBase = blockIdx.y * TCO;
    const int nBase  = blockIdx.z * NB;
    const int oy0 = tileY * TPH;
    const int ox0 = tileX * TPW;

    const int co0 = (tid % (TCO / CO_T)) * CO_T;
    const int pg  = tid / (TCO / CO_T);
    const int img = pg / (TPH * SEG);
    const int rem = pg % (TPH * SEG);
    const int py  = rem / SEG;
    const int px0 = (rem % SEG) * PX_T;

    unsigned long long aM[CP][PX_T], aV[CP][PX_T];
    #pragma unroll
    for (int p = 0; p < CP; p++)
        #pragma unroll
        for (int i = 0; i < PX_T; i++) { aM[p][i] = 0ull; aV[p][i] = 0ull; }

    #pragma unroll 1
    for (int c0 = 0; c0 < CIN; c0 += CK) {
        // stage input patch (zero padded)
        for (int idx = tid; idx < XS_N; idx += THREADS) {
            int im = idx / (CK * IPH * IPW);
            int r  = idx - im * (CK * IPH * IPW);
            int ck = r / (IPH * IPW);
            int r2 = r - ck * (IPH * IPW);
            int iy = r2 / IPW;
            int ix = r2 - iy * IPW;
            int gy = oy0 * S - 1 + iy;
            int gx = ox0 * S - 1 + ix;
            float v = 0.f;
            if (gy >= 0 && gy < HIN && gx >= 0 && gx < WIN)
                v = in[(((nBase + im) * CIN + (c0 + ck)) * HIN + gy) * WIN + gx];
            xs[idx] = v;
        }
        // stage weights transposed to [ck][tap][co]
        for (int idx = tid; idx < WS_N; idx += THREADS) {
            int ck  = idx / (9 * TCO);
            int rm  = idx - ck * (9 * TCO);
            int tap = rm / TCO;
            int co  = rm - tap * TCO;
            int g = ((coBase + co) * CIN + (c0 + ck)) * 9 + tap;
            wsm[idx] = wm[g];
            wsv[idx] = wv[g];
        }
        __syncthreads();

        #pragma unroll 1
        for (int ck = 0; ck < CK; ck++) {
            #pragma unroll
            for (int ky = 0; ky < 3; ky++) {
                const float* xrow = &xs[((img * CK + ck) * IPH + (py * S + ky)) * IPW + px0 * S];
                float4 f4[NF4];
                #pragma unroll
                for (int j = 0; j < NF4; j++)
                    f4[j] = reinterpret_cast<const float4*>(xrow)[j];
                const float* xv = reinterpret_cast<const float*>(f4);
                unsigned long long xp[NXV], xxp[NXV];
                #pragma unroll
                for (int j = 0; j < NXV; j++) {
                    xp[j]  = bcast2(xv[j]);
                    xxp[j] = mul2(xp[j], xp[j]);
                }
                #pragma unroll
                for (int kx = 0; kx < 3; kx++) {
                    const int tap = ky * 3 + kx;
                    unsigned long long wpm[CP], wpv[CP];
                    #pragma unroll
                    for (int j = 0; j < CO_T / 4; j++) {
                        ulonglong2 m2 = reinterpret_cast<const ulonglong2*>(&wsm[(ck * 9 + tap) * TCO + co0])[j];
                        ulonglong2 v2 = reinterpret_cast<const ulonglong2*>(&wsv[(ck * 9 + tap) * TCO + co0])[j];
                        wpm[2 * j] = m2.x; wpm[2 * j + 1] = m2.y;
                        wpv[2 * j] = v2.x; wpv[2 * j + 1] = v2.y;
                    }
                    #pragma unroll
                    for (int p = 0; p < CP; p++)
                        #pragma unroll
                        for (int i = 0; i < PX_T; i++) {
                            fma2(aM[p][i], wpm[p], xp[kx + i * S]);
                            fma2(aV[p][i], wpv[p], xxp[kx + i * S]);
                        }
                }
            }
        }
        __syncthreads();
    }

    const int n = nBase + img;
    const int oy = oy0 + py;
    #pragma unroll
    for (int p = 0; p < CP; p++) {
        const int cA = coBase + co0 + 2 * p;
        const float bA = bias[cA];
        const float bB = bias[cA + 1];
        const int oBaseA = ((n * COUT + cA) * HO + oy) * WO + ox0 + px0;
        #pragma unroll
        for (int i = 0; i < PX_T; i++) {
            float mA, mB, vA, vB;
            unpack2(aM[p][i], mA, mB);
            unpack2(aV[p][i], vA, vB);
            mA += bA; mB += bB;
            int oA = oBaseA + i;
            int oB = oA + HO * WO;
            if (LAST) {
                out[oA] = mA + sqrtf(vA + EPS) * noise[oA];
                out[oB] = mB + sqrtf(vB + EPS) * noise[oB];
            } else {
                out[oA] = erff(mA * rsqrtf(2.f * (vA + EPS)));
                out[oB] = erff(mB * rsqrtf(2.f * (vB + EPS)));
            }
        }
    }
}

// ---------------- batchnorm stats (per channel over n,h,w) ----------------
__global__ void bn_stats(const float* __restrict__ z, const float* __restrict__ gamma,
                         const float* __restrict__ beta, float* __restrict__ scale,
                         float* __restrict__ shift)
{
    __shared__ double ssum[256], ssq[256];
    int c = blockIdx.x;
    int t = threadIdx.x;
    double s = 0.0, s2 = 0.0;
    for (int i = t; i < 4096; i += 256) {
        int n = i >> 4, qq = i & 15;
        float v = z[(n * 512 + c) * 16 + qq];
        s  += v;
        s2 += (double)v * v;
    }
    ssum[t] = s; ssq[t] = s2;
    __syncthreads();
    for (int off = 128; off > 0; off >>= 1) {
        if (t < off) { ssum[t] += ssum[t + off]; ssq[t] += ssq[t + off]; }
        __syncthreads();
    }
    if (t == 0) {
        double mean = ssum[0] / 4096.0;
        double var  = ssq[0] / 4096.0 - mean * mean;
        float sc = gamma[c] * rsqrtf((float)var + EPS);
        scale[c] = sc;
        shift[c] = beta[c] - (float)mean * sc;
    }
}

__global__ void bn_norm(const float* __restrict__ z, const float* __restrict__ scale,
                        const float* __restrict__ shift, float* __restrict__ out)
{
    int idx = blockIdx.x * blockDim.x + threadIdx.x;
    if (idx < 256 * 8192) {
        int c = (idx >> 4) & 511;
        float v = z[idx] * scale[c] + shift[c];
        out[idx] = v > 0.f ? v : 0.f;
    }
}

// ---------------- FC1: [256,8192] x [1024,8192]^T, +bias, relu ----------------
__global__ void __launch_bounds__(256)
fc1_kernel(const float* __restrict__ A, const float* __restrict__ W,
           const float* __restrict__ bias, float* __restrict__ C)
{
    __shared__ float As[64][33];
    __shared__ float Ws[64][33];
    const int t = threadIdx.x;
    const int mBlk = blockIdx.y * 64, nBlk = blockIdx.x * 64;
    const int msub = (t % 16) * 4, nsub = (t / 16) * 4;
    float acc[4][4];
    #pragma unroll
    for (int i = 0; i < 4; i++)
        #pragma unroll
        for (int j = 0; j < 4; j++) acc[i][j] = 0.f;

    for (int k0 = 0; k0 < 8192; k0 += 32) {
        for (int i = t; i < 64 * 32; i += 256) {
            int r = i >> 5, kk = i & 31;
            As[r][kk] = A[(mBlk + r) * 8192 + k0 + kk];
            Ws[r][kk] = W[(nBlk + r) * 8192 + k0 + kk];
        }
        __syncthreads();
        #pragma unroll
        for (int kk = 0; kk < 32; kk++) {
            float a0 = As[msub][kk], a1 = As[msub + 1][kk], a2 = As[msub + 2][kk], a3 = As[msub + 3][kk];
            float w0 = Ws[nsub][kk], w1 = Ws[nsub + 1][kk], w2 = Ws[nsub + 2][kk], w3 = Ws[nsub + 3][kk];
            acc[0][0] += a0 * w0; acc[0][1] += a0 * w1; acc[0][2] += a0 * w2; acc[0][3] += a0 * w3;
            acc[1][0] += a1 * w0; acc[1][1] += a1 * w1; acc[1][2] += a1 * w2; acc[1][3] += a1 * w3;
            acc[2][0] += a2 * w0; acc[2][1] += a2 * w1; acc[2][2] += a2 * w2; acc[2][3] += a2 * w3;
            acc[3][0] += a3 * w0; acc[3][1] += a3 * w1; acc[3][2] += a3 * w2; acc[3][3] += a3 * w3;
        }
        __syncthreads();
    }
    #pragma unroll
    for (int i = 0; i < 4; i++)
        #pragma unroll
        for (int j = 0; j < 4; j++) {
            float v = acc[i][j] + bias[nBlk + nsub + j];
            C[(mBlk + msub + i) * 1024 + nBlk + nsub + j] = v > 0.f ? v : 0.f;
        }
}

// ---------------- FC2: [256,1024] x [10,1024]^T + bias ----------------
__global__ void fc2_kernel(const float* __restrict__ A, const float* __restrict__ W,
                           const float* __restrict__ bias, float* __restrict__ out)
{
    int idx = blockIdx.x * blockDim.x + threadIdx.x;
    if (idx >= 2560) return;
    int n = idx / 10, j = idx - n * 10;
    const float* a = A + n * 1024;
    const float* w = W + j * 1024;
    float s = bias[j];
    for (int k = 0; k < 1024; k += 4)
        s += a[k] * w[k] + a[k + 1] * w[k + 1] + a[k + 2] * w[k + 2] + a[k + 3] * w[k + 3];
    out[idx] = s;
}

// ---------------- launch ----------------
extern "C" void kernel_launch(void* const* d_in, const int* in_sizes, int n_in,
                              void* d_out, int out_size)
{
    (void)in_sizes; (void)n_in; (void)out_size;
    const float* x = (const float*)d_in[0];
    const float* a[6]  = {(const float*)d_in[1],  (const float*)d_in[4],  (const float*)d_in[7],
                          (const float*)d_in[10], (const float*)d_in[13], (const float*)d_in[16]};
    const float* bt[6] = {(const float*)d_in[2],  (const float*)d_in[5],  (const float*)d_in[8],
                          (const float*)d_in[11], (const float*)d_in[14], (const float*)d_in[17]};
    const float* cb[6] = {(const float*)d_in[3],  (const float*)d_in[6],  (const float*)d_in[9],
                          (const float*)d_in[12], (const float*)d_in[15], (const float*)d_in[18]};
    const float* gamma = (const float*)d_in[19];
    const float* beta  = (const float*)d_in[20];
    const float* fc1w  = (const float*)d_in[21];
    const float* fc1b  = (const float*)d_in[22];
    const float* fc2w  = (const float*)d_in[23];
    const float* fc2b  = (const float*)d_in[24];
    const float* noise = (const float*)d_in[25];

    float *wm[6], *wv[6];
    cudaGetSymbolAddress((void**)&wm[0], g_wm1); cudaGetSymbolAddress((void**)&wv[0], g_wv1);
    cudaGetSymbolAddress((void**)&wm[1], g_wm2); cudaGetSymbolAddress((void**)&wv[1], g_wv2);
    cudaGetSymbolAddress((void**)&wm[2], g_wm3); cudaGetSymbolAddress((void**)&wv[2], g_wv3);
    cudaGetSymbolAddress((void**)&wm[3], g_wm4); cudaGetSymbolAddress((void**)&wv[3], g_wv4);
    cudaGetSymbolAddress((void**)&wm[4], g_wm5); cudaGetSymbolAddress((void**)&wv[4], g_wv5);
    cudaGetSymbolAddress((void**)&wm[5], g_wm6); cudaGetSymbolAddress((void**)&wv[5], g_wv6);

    float *h1, *h2, *h3, *h4, *h5, *z6, *zbn, *fc1o, *scale, *shift;
    cudaGetSymbolAddress((void**)&h1,  g_h1);
    cudaGetSymbolAddress((void**)&h2,  g_h2);
    cudaGetSymbolAddress((void**)&h3,  g_h3);
    cudaGetSymbolAddress((void**)&h4,  g_h4);
    cudaGetSymbolAddress((void**)&h5,  g_h5);
    cudaGetSymbolAddress((void**)&z6,  g_z6);
    cudaGetSymbolAddress((void**)&zbn, g_zbn);
    cudaGetSymbolAddress((void**)&fc1o, g_fc1o);
    cudaGetSymbolAddress((void**)&scale, g_bnscale);
    cudaGetSymbolAddress((void**)&shift, g_bnshift);

    // launch 0: all weight preprocessing
    prep_all<<<(4574592 + 255) / 256, 256>>>(a[0], bt[0], a[1], bt[1], a[2], bt[2],
                                             a[3], bt[3], a[4], bt[4], a[5], bt[5]);

    // launch 1: L1: 3->128, 32x32, s1 (4co x 8px)
    conv_lr2<3, 128, 32, 32, 1, 8, 8, 2, 3, 4, 8, false, 128>
        <<<dim3(16, 4, 128), 128>>>(x, wm[0], wv[0], cb[0], h1, nullptr);
    // launch 2: L2: 128->128, 32->16, s2 (8co x 4px)
    conv_lr2<128, 128, 32, 32, 2, 8, 8, 2, 8, 8, 4, false, 128>
        <<<dim3(4, 4, 128), 128>>>(h1, wm[1], wv[1], cb[1], h2, nullptr);
    // launch 3: L3: 128->256, 16x16, s1 (4co x 8px)
    conv_lr2<128, 256, 16, 16, 1, 8, 8, 2, 8, 4, 8, false, 128>
        <<<dim3(4, 8, 128), 128>>>(h2, wm[2], wv[2], cb[2], h3, nullptr);
    // launch 4: L4: 256->256, 16->8, s2 (8co x 4px, NB=4)
    conv_lr2<256, 256, 16, 16, 2, 4, 8, 4, 8, 8, 4, false, 128>
        <<<dim3(2, 8, 64), 128>>>(h3, wm[3], wv[3], cb[3], h4, nullptr);
    // launch 5: L5: 256->512, 8x8, s1 (4co x 8px, NB=4)  <- ncu -s 5 target
    conv_lr2<256, 512, 8, 8, 1, 4, 8, 4, 8, 4, 8, false, 128>
        <<<dim3(2, 16, 64), 128>>>(h4, wm[4], wv[4], cb[4], h5, nullptr);
    // launch 6: L6: 512->512, 8->4, s2, sampled (8co x 4px, NB=8)
    conv_lr2<512, 512, 8, 8, 2, 4, 4, 8, 8, 8, 4, true, 128>
        <<<dim3(1, 16, 32), 128>>>(h5, wm[5], wv[5], cb[5], z6, noise);

    bn_stats<<<512, 256>>>(z6, gamma, beta, scale, shift);
    bn_norm<<<(2097152 + 255) / 256, 256>>>(z6, scale, shift, zbn);
    fc1_kernel<<<dim3(16, 4), 256>>>(zbn, fc1w, fc1b, fc1o);
    fc2_kernel<<<(2560 + 127) / 128, 128>>>(fc1o, fc2w, fc2b, (float*)d_out);
}

// round 4
// speedup vs baseline: 1.6234x; 1.6234x over previous
#include <cuda_runtime.h>
#include <math.h>

#define EPS 1e-5f

// ---------------- device scratch (no runtime allocation allowed) ----------------
__device__ float g_wm1[3456],    g_wv1[3456];
__device__ float g_wm2[147456],  g_wv2[147456];
__device__ float g_wm3[294912],  g_wv3[294912];
__device__ float g_wm4[589824],  g_wv4[589824];
__device__ float g_wm5[1179648], g_wv5[1179648];
__device__ float g_wm6[2359296], g_wv6[2359296];

__device__ float g_h1[33554432];  // [256,128,32,32]
__device__ float g_h2[8388608];   // [256,128,16,16]
__device__ float g_h3[16777216];  // [256,256,16,16]
__device__ float g_h4[4194304];   // [256,256,8,8]
__device__ float g_h5[8388608];   // [256,512,8,8]
__device__ float g_z6[2097152];   // [256,512,4,4]
__device__ float g_zbn[2097152];  // [256,8192]
__device__ float g_fc1o[262144];  // [256,1024]
__device__ float g_bnscale[512], g_bnshift[512];

// ---------------- packed f32x2 helpers ----------------
__device__ __forceinline__ unsigned long long bcast2(float x) {
    unsigned long long r;
    unsigned u = __float_as_uint(x);
    asm("mov.b64 %0, {%1, %1};" : "=l"(r) : "r"(u));
    return r;
}
__device__ __forceinline__ unsigned long long mul2(unsigned long long a, unsigned long long b) {
    unsigned long long d;
    asm("mul.rn.f32x2 %0, %1, %2;" : "=l"(d) : "l"(a), "l"(b));
    return d;
}
__device__ __forceinline__ void fma2(unsigned long long& d, unsigned long long a, unsigned long long b) {
    asm("fma.rn.f32x2 %0, %1, %2, %0;" : "+l"(d) : "l"(a), "l"(b));
}
__device__ __forceinline__ void unpack2(unsigned long long v, float& lo, float& hi) {
    unsigned ulo, uhi;
    asm("mov.b64 {%0, %1}, %2;" : "=r"(ulo), "=r"(uhi) : "l"(v));
    lo = __uint_as_float(ulo); hi = __uint_as_float(uhi);
}

// ---------------- weight distribution preprocessing (one launch) ----------------
__global__ void prep_all(const float* __restrict__ a1, const float* __restrict__ b1,
                         const float* __restrict__ a2, const float* __restrict__ b2,
                         const float* __restrict__ a3, const float* __restrict__ b3,
                         const float* __restrict__ a4, const float* __restrict__ b4,
                         const float* __restrict__ a5, const float* __restrict__ b5,
                         const float* __restrict__ a6, const float* __restrict__ b6)
{
    int i = blockIdx.x * blockDim.x + threadIdx.x;
    if (i >= 4574592) return;
    const float *A, *Bp; float *WM, *WV; int j;
    if (i < 150912) {
        if (i < 3456) { A = a1; Bp = b1; WM = g_wm1; WV = g_wv1; j = i; }
        else          { A = a2; Bp = b2; WM = g_wm2; WV = g_wv2; j = i - 3456; }
    } else if (i < 1035648) {
        if (i < 445824) { A = a3; Bp = b3; WM = g_wm3; WV = g_wv3; j = i - 150912; }
        else            { A = a4; Bp = b4; WM = g_wm4; WV = g_wv4; j = i - 445824; }
    } else {
        if (i < 2215296) { A = a5; Bp = b5; WM = g_wm5; WV = g_wv5; j = i - 1035648; }
        else             { A = a6; Bp = b6; WM = g_wm6; WV = g_wv6; j = i - 2215296; }
    }
    float p0 = 1.f / (1.f + expf(-A[j]));
    float sb = 1.f / (1.f + expf(-Bp[j]));
    float p1 = (1.f - p0) * sb;
    float m  = 2.f * p1 + p0 - 1.f;
    WM[j] = m;
    WV[j] = (1.f - p0) - m * m;
}

// ---------------- fused LR-conv layer, v2 microtile ----------------
// Each thread: CO_T output channels x PX_T consecutive output pixels (one row seg).
// m = conv(x, w_mean)+bias ; v = conv(x*x, w_var)
// LAST=false: out = erf(m / sqrt(2*(v+EPS)))   LAST=true: out = m + sqrt(v+EPS)*noise
template<int CIN, int COUT, int HIN, int WIN, int S, int TPH, int TPW, int NB,
         int CK, int CO_T, int PX_T, bool LAST, int THREADS>
__global__ void __launch_bounds__(THREADS)
conv_lr2(const float* __restrict__ in, const float* __restrict__ wm,
         const float* __restrict__ wv, const float* __restrict__ bias,
         float* __restrict__ out, const float* __restrict__ noise)
{
    constexpr int TCO  = 32;
    constexpr int HO   = HIN / S;
    constexpr int WO   = WIN / S;
    constexpr int IPH  = (TPH - 1) * S + 3;
    constexpr int IPW  = (((TPW - 1) * S + 3) + 3) & ~3;   // padded to 16B
    constexpr int SEG  = TPW / PX_T;
    constexpr int XS_N = NB * CK * IPH * IPW;
    constexpr int WS_N = CK * 9 * TCO;
    constexpr int NXV  = (PX_T - 1) * S + 3;               // x values per row needed
    constexpr int NF4  = (NXV + 3) / 4;
    constexpr int CP   = CO_T / 2;                         // channel pairs
    static_assert(THREADS == (TCO / CO_T) * (NB * TPH * SEG), "thread count mismatch");
    static_assert(NF4 * 4 <= IPW, "x vector load overruns row");
    static_assert((PX_T * S) % 4 == 0, "segment start misaligned");

    __shared__ __align__(16) float xs[XS_N];
    __shared__ __align__(16) float wsm[WS_N];
    __shared__ __align__(16) float wsv[WS_N];

    const int tid = threadIdx.x;
    constexpr int TILESX = WO / TPW;
    const int tileX  = blockIdx.x % TILESX;
    const int tileY  = blockIdx.x / TILESX;
    const int coBase = blockIdx.y * TCO;
    const int nBase  = blockIdx.z * NB;
    const int oy0 = tileY * TPH;
    const int ox0 = tileX * TPW;

    const int co0 = (tid % (TCO / CO_T)) * CO_T;
    const int pg  = tid / (TCO / CO_T);
    const int img = pg / (TPH * SEG);
    const int rem = pg % (TPH * SEG);
    const int py  = rem / SEG;
    const int px0 = (rem % SEG) * PX_T;

    unsigned long long aM[CP][PX_T], aV[CP][PX_T];
    #pragma unroll
    for (int p = 0; p < CP; p++)
        #pragma unroll
        for (int i = 0; i < PX_T; i++) { aM[p][i] = 0ull; aV[p][i] = 0ull; }

    #pragma unroll 1
    for (int c0 = 0; c0 < CIN; c0 += CK) {
        // stage input patch (zero padded)
        for (int idx = tid; idx < XS_N; idx += THREADS) {
            int im = idx / (CK * IPH * IPW);
            int r  = idx - im * (CK * IPH * IPW);
            int ck = r / (IPH * IPW);
            int r2 = r - ck * (IPH * IPW);
            int iy = r2 / IPW;
            int ix = r2 - iy * IPW;
            int gy = oy0 * S - 1 + iy;
            int gx = ox0 * S - 1 + ix;
            float v = 0.f;
            if (gy >= 0 && gy < HIN && gx >= 0 && gx < WIN)
                v = in[(((nBase + im) * CIN + (c0 + ck)) * HIN + gy) * WIN + gx];
            xs[idx] = v;
        }
        // stage weights transposed to [ck][tap][co]
        for (int idx = tid; idx < WS_N; idx += THREADS) {
            int ck  = idx / (9 * TCO);
            int rm  = idx - ck * (9 * TCO);
            int tap = rm / TCO;
            int co  = rm - tap * TCO;
            int g = ((coBase + co) * CIN + (c0 + ck)) * 9 + tap;
            wsm[idx] = wm[g];
            wsv[idx] = wv[g];
        }
        __syncthreads();

        #pragma unroll 1
        for (int ck = 0; ck < CK; ck++) {
            #pragma unroll
            for (int ky = 0; ky < 3; ky++) {
                const float* xrow = &xs[((img * CK + ck) * IPH + (py * S + ky)) * IPW + px0 * S];
                float4 f4[NF4];
                #pragma unroll
                for (int j = 0; j < NF4; j++)
                    f4[j] = reinterpret_cast<const float4*>(xrow)[j];
                const float* xv = reinterpret_cast<const float*>(f4);
                unsigned long long xp[NXV], xxp[NXV];
                #pragma unroll
                for (int j = 0; j < NXV; j++) {
                    xp[j]  = bcast2(xv[j]);
                    xxp[j] = mul2(xp[j], xp[j]);
                }
                #pragma unroll
                for (int kx = 0; kx < 3; kx++) {
                    const int tap = ky * 3 + kx;
                    unsigned long long wpm[CP], wpv[CP];
                    #pragma unroll
                    for (int j = 0; j < CO_T / 4; j++) {
                        ulonglong2 m2 = reinterpret_cast<const ulonglong2*>(&wsm[(ck * 9 + tap) * TCO + co0])[j];
                        ulonglong2 v2 = reinterpret_cast<const ulonglong2*>(&wsv[(ck * 9 + tap) * TCO + co0])[j];
                        wpm[2 * j] = m2.x; wpm[2 * j + 1] = m2.y;
                        wpv[2 * j] = v2.x; wpv[2 * j + 1] = v2.y;
                    }
                    #pragma unroll
                    for (int p = 0; p < CP; p++)
                        #pragma unroll
                        for (int i = 0; i < PX_T; i++) {
                            fma2(aM[p][i], wpm[p], xp[kx + i * S]);
                            fma2(aV[p][i], wpv[p], xxp[kx + i * S]);
                        }
                }
            }
        }
        __syncthreads();
    }

    const int n = nBase + img;
    const int oy = oy0 + py;
    #pragma unroll
    for (int p = 0; p < CP; p++) {
        const int cA = coBase + co0 + 2 * p;
        const float bA = bias[cA];
        const float bB = bias[cA + 1];
        const int oBaseA = ((n * COUT + cA) * HO + oy) * WO + ox0 + px0;
        #pragma unroll
        for (int i = 0; i < PX_T; i++) {
            float mA, mB, vA, vB;
            unpack2(aM[p][i], mA, mB);
            unpack2(aV[p][i], vA, vB);
            mA += bA; mB += bB;
            int oA = oBaseA + i;
            int oB = oA + HO * WO;
            if (LAST) {
                out[oA] = mA + sqrtf(vA + EPS) * noise[oA];
                out[oB] = mB + sqrtf(vB + EPS) * noise[oB];
            } else {
                out[oA] = erff(mA * rsqrtf(2.f * (vA + EPS)));
                out[oB] = erff(mB * rsqrtf(2.f * (vB + EPS)));
            }
        }
    }
}

// ---------------- batchnorm stats (per channel over n,h,w) ----------------
__global__ void bn_stats(const float* __restrict__ z, const float* __restrict__ gamma,
                         const float* __restrict__ beta, float* __restrict__ scale,
                         float* __restrict__ shift)
{
    __shared__ double ssum[256], ssq[256];
    int c = blockIdx.x;
    int t = threadIdx.x;
    double s = 0.0, s2 = 0.0;
    for (int i = t; i < 4096; i += 256) {
        int n = i >> 4, qq = i & 15;
        float v = z[(n * 512 + c) * 16 + qq];
        s  += v;
        s2 += (double)v * v;
    }
    ssum[t] = s; ssq[t] = s2;
    __syncthreads();
    for (int off = 128; off > 0; off >>= 1) {
        if (t < off) { ssum[t] += ssum[t + off]; ssq[t] += ssq[t + off]; }
        __syncthreads();
    }
    if (t == 0) {
        double mean = ssum[0] / 4096.0;
        double var  = ssq[0] / 4096.0 - mean * mean;
        float sc = gamma[c] * rsqrtf((float)var + EPS);
        scale[c] = sc;
        shift[c] = beta[c] - (float)mean * sc;
    }
}

__global__ void bn_norm(const float* __restrict__ z, const float* __restrict__ scale,
                        const float* __restrict__ shift, float* __restrict__ out)
{
    int idx = blockIdx.x * blockDim.x + threadIdx.x;
    if (idx < 256 * 8192) {
        int c = (idx >> 4) & 511;
        float v = z[idx] * scale[c] + shift[c];
        out[idx] = v > 0.f ? v : 0.f;
    }
}

// ---------------- FC1: [256,8192] x [1024,8192]^T, +bias, relu ----------------
__global__ void __launch_bounds__(256)
fc1_kernel(const float* __restrict__ A, const float* __restrict__ W,
           const float* __restrict__ bias, float* __restrict__ C)
{
    __shared__ float As[64][33];
    __shared__ float Ws[64][33];
    const int t = threadIdx.x;
    const int mBlk = blockIdx.y * 64, nBlk = blockIdx.x * 64;
    const int msub = (t % 16) * 4, nsub = (t / 16) * 4;
    float acc[4][4];
    #pragma unroll
    for (int i = 0; i < 4; i++)
        #pragma unroll
        for (int j = 0; j < 4; j++) acc[i][j] = 0.f;

    for (int k0 = 0; k0 < 8192; k0 += 32) {
        for (int i = t; i < 64 * 32; i += 256) {
            int r = i >> 5, kk = i & 31;
            As[r][kk] = A[(mBlk + r) * 8192 + k0 + kk];
            Ws[r][kk] = W[(nBlk + r) * 8192 + k0 + kk];
        }
        __syncthreads();
        #pragma unroll
        for (int kk = 0; kk < 32; kk++) {
            float a0 = As[msub][kk], a1 = As[msub + 1][kk], a2 = As[msub + 2][kk], a3 = As[msub + 3][kk];
            float w0 = Ws[nsub][kk], w1 = Ws[nsub + 1][kk], w2 = Ws[nsub + 2][kk], w3 = Ws[nsub + 3][kk];
            acc[0][0] += a0 * w0; acc[0][1] += a0 * w1; acc[0][2] += a0 * w2; acc[0][3] += a0 * w3;
            acc[1][0] += a1 * w0; acc[1][1] += a1 * w1; acc[1][2] += a1 * w2; acc[1][3] += a1 * w3;
            acc[2][0] += a2 * w0; acc[2][1] += a2 * w1; acc[2][2] += a2 * w2; acc[2][3] += a2 * w3;
            acc[3][0] += a3 * w0; acc[3][1] += a3 * w1; acc[3][2] += a3 * w2; acc[3][3] += a3 * w3;
        }
        __syncthreads();
    }
    #pragma unroll
    for (int i = 0; i < 4; i++)
        #pragma unroll
        for (int j = 0; j < 4; j++) {
            float v = acc[i][j] + bias[nBlk + nsub + j];
            C[(mBlk + msub + i) * 1024 + nBlk + nsub + j] = v > 0.f ? v : 0.f;
        }
}

// ---------------- FC2: [256,1024] x [10,1024]^T + bias ----------------
__global__ void fc2_kernel(const float* __restrict__ A, const float* __restrict__ W,
                           const float* __restrict__ bias, float* __restrict__ out)
{
    int idx = blockIdx.x * blockDim.x + threadIdx.x;
    if (idx >= 2560) return;
    int n = idx / 10, j = idx - n * 10;
    const float* a = A + n * 1024;
    const float* w = W + j * 1024;
    float s = bias[j];
    for (int k = 0; k < 1024; k += 4)
        s += a[k] * w[k] + a[k + 1] * w[k + 1] + a[k + 2] * w[k + 2] + a[k + 3] * w[k + 3];
    out[idx] = s;
}

// ---------------- launch ----------------
extern "C" void kernel_launch(void* const* d_in, const int* in_sizes, int n_in,
                              void* d_out, int out_size)
{
    (void)in_sizes; (void)n_in; (void)out_size;
    const float* x = (const float*)d_in[0];
    const float* a[6]  = {(const float*)d_in[1],  (const float*)d_in[4],  (const float*)d_in[7],
                          (const float*)d_in[10], (const float*)d_in[13], (const float*)d_in[16]};
    const float* bt[6] = {(const float*)d_in[2],  (const float*)d_in[5],  (const float*)d_in[8],
                          (const float*)d_in[11], (const float*)d_in[14], (const float*)d_in[17]};
    const float* cb[6] = {(const float*)d_in[3],  (const float*)d_in[6],  (const float*)d_in[9],
                          (const float*)d_in[12], (const float*)d_in[15], (const float*)d_in[18]};
    const float* gamma = (const float*)d_in[19];
    const float* beta  = (const float*)d_in[20];
    const float* fc1w  = (const float*)d_in[21];
    const float* fc1b  = (const float*)d_in[22];
    const float* fc2w  = (const float*)d_in[23];
    const float* fc2b  = (const float*)d_in[24];
    const float* noise = (const float*)d_in[25];

    float *wm[6], *wv[6];
    cudaGetSymbolAddress((void**)&wm[0], g_wm1); cudaGetSymbolAddress((void**)&wv[0], g_wv1);
    cudaGetSymbolAddress((void**)&wm[1], g_wm2); cudaGetSymbolAddress((void**)&wv[1], g_wv2);
    cudaGetSymbolAddress((void**)&wm[2], g_wm3); cudaGetSymbolAddress((void**)&wv[2], g_wv3);
    cudaGetSymbolAddress((void**)&wm[3], g_wm4); cudaGetSymbolAddress((void**)&wv[3], g_wv4);
    cudaGetSymbolAddress((void**)&wm[4], g_wm5); cudaGetSymbolAddress((void**)&wv[4], g_wv5);
    cudaGetSymbolAddress((void**)&wm[5], g_wm6); cudaGetSymbolAddress((void**)&wv[5], g_wv6);

    float *h1, *h2, *h3, *h4, *h5, *z6, *zbn, *fc1o, *scale, *shift;
    cudaGetSymbolAddress((void**)&h1,  g_h1);
    cudaGetSymbolAddress((void**)&h2,  g_h2);
    cudaGetSymbolAddress((void**)&h3,  g_h3);
    cudaGetSymbolAddress((void**)&h4,  g_h4);
    cudaGetSymbolAddress((void**)&h5,  g_h5);
    cudaGetSymbolAddress((void**)&z6,  g_z6);
    cudaGetSymbolAddress((void**)&zbn, g_zbn);
    cudaGetSymbolAddress((void**)&fc1o, g_fc1o);
    cudaGetSymbolAddress((void**)&scale, g_bnscale);
    cudaGetSymbolAddress((void**)&shift, g_bnshift);

    // launch 0: all weight preprocessing
    prep_all<<<(4574592 + 255) / 256, 256>>>(a[0], bt[0], a[1], bt[1], a[2], bt[2],
                                             a[3], bt[3], a[4], bt[4], a[5], bt[5]);

    // launch 1: L1: 3->128, 32x32, s1 (4co x 8px)
    conv_lr2<3, 128, 32, 32, 1, 8, 8, 2, 3, 4, 8, false, 128>
        <<<dim3(16, 4, 128), 128>>>(x, wm[0], wv[0], cb[0], h1, nullptr);
    // launch 2: L2: 128->128, 32->16, s2 (8co x 4px)
    conv_lr2<128, 128, 32, 32, 2, 8, 8, 2, 8, 8, 4, false, 128>
        <<<dim3(4, 4, 128), 128>>>(h1, wm[1], wv[1], cb[1], h2, nullptr);
    // launch 3: L3: 128->256, 16x16, s1 (4co x 8px)
    conv_lr2<128, 256, 16, 16, 1, 8, 8, 2, 8, 4, 8, false, 128>
        <<<dim3(4, 8, 128), 128>>>(h2, wm[2], wv[2], cb[2], h3, nullptr);
    // launch 4: L4: 256->256, 16->8, s2 (8co x 4px, NB=4)
    conv_lr2<256, 256, 16, 16, 2, 4, 8, 4, 8, 8, 4, false, 128>
        <<<dim3(2, 8, 64), 128>>>(h3, wm[3], wv[3], cb[3], h4, nullptr);
    // launch 5: L5: 256->512, 8x8, s1 (4co x 8px, NB=4)  <- ncu -s 5 target
    conv_lr2<256, 512, 8, 8, 1, 4, 8, 4, 8, 4, 8, false, 128>
        <<<dim3(2, 16, 64), 128>>>(h4, wm[4], wv[4], cb[4], h5, nullptr);
    // launch 6: L6: 512->512, 8->4, s2, sampled (8co x 4px, NB=8)
    conv_lr2<512, 512, 8, 8, 2, 4, 4, 8, 8, 8, 4, true, 128>
        <<<dim3(1, 16, 32), 128>>>(h5, wm[5], wv[5], cb[5], z6, noise);

    bn_stats<<<512, 256>>>(z6, gamma, beta, scale, shift);
    bn_norm<<<(2097152 + 255) / 256, 256>>>(z6, scale, shift, zbn);
    fc1_kernel<<<dim3(16, 4), 256>>>(zbn, fc1w, fc1b, fc1o);
    fc2_kernel<<<(2560 + 127) / 128, 128>>>(fc1o, fc2w, fc2b, (float*)d_out);
}